// round 1
// baseline (speedup 1.0000x reference)
#include <cuda_runtime.h>
#include <math.h>

// Problem dims
#define Bsz  4
#define Nseq 2048
#define Dmod 512
#define Hh   8
#define DHd  64
#define FFd  1024
#define Mrows (Bsz*Nseq)   // 8192

// ---------------- scratch (static device allocations) ----------------
__device__ float g_qk0[Mrows*Dmod];
__device__ float g_qk1[Mrows*Dmod];
__device__ float g_v0 [Mrows*Dmod];
__device__ float g_v1 [Mrows*Dmod];
__device__ float g_a0 [Mrows*Dmod];
__device__ float g_a1 [Mrows*Dmod];
__device__ float g_hcat[Mrows*FFd];
__device__ float g_hmid[Mrows*FFd];

// ---------------- SGEMM: C[M,N] = A[M,K] * W[N,K]^T + bias (+res) ----------------
// 128x128 block tile, BK=8, 8x8 per-thread tile, 256 threads.
__global__ __launch_bounds__(256) void sgemm_bias_kernel(
    const float* __restrict__ A, const float* __restrict__ W,
    const float* __restrict__ bias, const float* __restrict__ res,
    float* __restrict__ C, int M, int N, int K)
{
    __shared__ float As[8][132];
    __shared__ float Ws[8][132];

    const int tid  = threadIdx.x;
    const int lrow = tid >> 1;          // 0..127
    const int lcol = (tid & 1) << 2;    // 0 or 4
    const int tr   = tid >> 4;          // 0..15
    const int tc   = tid & 15;          // 0..15

    const float* Ag = A + (size_t)blockIdx.y * 128 * K;
    const float* Wg = W + (size_t)blockIdx.x * 128 * K;

    float acc[8][8];
    #pragma unroll
    for (int i = 0; i < 8; i++)
        #pragma unroll
        for (int j = 0; j < 8; j++) acc[i][j] = 0.f;

    for (int k0 = 0; k0 < K; k0 += 8) {
        float4 a4 = *reinterpret_cast<const float4*>(Ag + (size_t)lrow * K + k0 + lcol);
        float4 w4 = *reinterpret_cast<const float4*>(Wg + (size_t)lrow * K + k0 + lcol);
        As[lcol+0][lrow] = a4.x; As[lcol+1][lrow] = a4.y;
        As[lcol+2][lrow] = a4.z; As[lcol+3][lrow] = a4.w;
        Ws[lcol+0][lrow] = w4.x; Ws[lcol+1][lrow] = w4.y;
        Ws[lcol+2][lrow] = w4.z; Ws[lcol+3][lrow] = w4.w;
        __syncthreads();

        #pragma unroll
        for (int k = 0; k < 8; k++) {
            float4 a0 = *reinterpret_cast<const float4*>(&As[k][tr*8]);
            float4 a1 = *reinterpret_cast<const float4*>(&As[k][tr*8+4]);
            float4 b0 = *reinterpret_cast<const float4*>(&Ws[k][tc*8]);
            float4 b1 = *reinterpret_cast<const float4*>(&Ws[k][tc*8+4]);
            float av[8] = {a0.x,a0.y,a0.z,a0.w,a1.x,a1.y,a1.z,a1.w};
            float bv[8] = {b0.x,b0.y,b0.z,b0.w,b1.x,b1.y,b1.z,b1.w};
            #pragma unroll
            for (int i = 0; i < 8; i++)
                #pragma unroll
                for (int j = 0; j < 8; j++) acc[i][j] += av[i]*bv[j];
        }
        __syncthreads();
    }

    const int mb = blockIdx.y*128 + tr*8;
    const int nb = blockIdx.x*128 + tc*8;
    #pragma unroll
    for (int i = 0; i < 8; i++) {
        float*       Crow = C + (size_t)(mb+i)*N + nb;
        const float* Rrow = res ? (res + (size_t)(mb+i)*N + nb) : nullptr;
        #pragma unroll
        for (int j = 0; j < 8; j++) {
            float v = acc[i][j] + bias[nb+j];
            if (Rrow) v += Rrow[j];
            Crow[j] = v;
        }
    }
}

// ---------------- Attention (flash-style, online softmax) ----------------
// grid = (B*H, N/64), 64 threads; each thread owns one query row.
// Q row + output accumulator in registers; K/V tiles (32 rows) in smem (broadcast reads).
__global__ __launch_bounds__(64) void attn_kernel(
    const float* __restrict__ Q, const float* __restrict__ Kt,
    const float* __restrict__ V, float* __restrict__ O)
{
    __shared__ float Ks[32][65];
    __shared__ float Vs[32][65];
    __shared__ float Ss[64][33];

    const int bh = blockIdx.x;
    const int qt = blockIdx.y;
    const int b  = bh / Hh;
    const int h  = bh % Hh;
    const size_t base = (size_t)b * Nseq * Dmod + (size_t)h * DHd;

    const int tid = threadIdx.x;
    const int row = qt * 64 + tid;

    float q[64], acc[64];
    #pragma unroll
    for (int d = 0; d < 64; d++) {
        q[d]   = Q[base + (size_t)row * Dmod + d];
        acc[d] = 0.f;
    }
    float mval = -INFINITY, lval = 0.f;

    for (int kt = 0; kt < Nseq/32; kt++) {
        __syncthreads();
        for (int i = tid; i < 32*64; i += 64) {
            int r = i >> 6, d = i & 63;
            Ks[r][d] = Kt[base + (size_t)(kt*32 + r) * Dmod + d];
            Vs[r][d] = V [base + (size_t)(kt*32 + r) * Dmod + d];
        }
        __syncthreads();

        float tmax = mval;
        #pragma unroll 4
        for (int j = 0; j < 32; j++) {
            float s = 0.f;
            #pragma unroll
            for (int d = 0; d < 64; d++) s += q[d] * Ks[j][d];
            s *= 0.125f;                 // 1/sqrt(64)
            Ss[tid][j] = s;
            tmax = fmaxf(tmax, s);
        }

        float corr = expf(mval - tmax);  // 0 on first tile (mval = -inf)
        mval = tmax;
        lval *= corr;
        #pragma unroll
        for (int d = 0; d < 64; d++) acc[d] *= corr;

        #pragma unroll 4
        for (int j = 0; j < 32; j++) {
            float p = expf(Ss[tid][j] - mval);
            lval += p;
            #pragma unroll
            for (int d = 0; d < 64; d++) acc[d] += p * Vs[j][d];
        }
    }

    float inv = 1.f / lval;
    #pragma unroll
    for (int d = 0; d < 64; d++)
        O[base + (size_t)row * Dmod + d] = acc[d] * inv;
}

// ---------------- concat [x | m] -> hcat [M, 1024] ----------------
__global__ void concat_kernel(const float* __restrict__ X, const float* __restrict__ Mm,
                              float* __restrict__ Out)
{
    int idx = blockIdx.x * blockDim.x + threadIdx.x;
    if (idx >= Mrows * FFd) return;
    int m = idx >> 10;
    int c = idx & 1023;
    Out[idx] = (c < Dmod) ? X[(size_t)m * Dmod + c] : Mm[(size_t)m * Dmod + (c - Dmod)];
}

// ---------------- LayerNorm(1024) + exact GELU, in place ----------------
__global__ __launch_bounds__(256) void ln_gelu_kernel(
    float* __restrict__ Hm, const float* __restrict__ gw, const float* __restrict__ bw)
{
    __shared__ float red1[8];
    __shared__ float red2[8];
    __shared__ float s_mu, s_inv;

    const int row = blockIdx.x;
    const int tid = threadIdx.x;
    float* hp = Hm + (size_t)row * FFd;

    float v[4];
    float s = 0.f;
    #pragma unroll
    for (int i = 0; i < 4; i++) { v[i] = hp[tid + i*256]; s += v[i]; }

    #pragma unroll
    for (int off = 16; off; off >>= 1) s += __shfl_xor_sync(0xffffffffu, s, off);
    if ((tid & 31) == 0) red1[tid >> 5] = s;
    __syncthreads();
    if (tid == 0) {
        float t = 0.f;
        #pragma unroll
        for (int w = 0; w < 8; w++) t += red1[w];
        s_mu = t * (1.f / FFd);
    }
    __syncthreads();
    const float mu = s_mu;

    float ss = 0.f;
    #pragma unroll
    for (int i = 0; i < 4; i++) { float d = v[i] - mu; ss += d*d; }
    #pragma unroll
    for (int off = 16; off; off >>= 1) ss += __shfl_xor_sync(0xffffffffu, ss, off);
    if ((tid & 31) == 0) red2[tid >> 5] = ss;
    __syncthreads();
    if (tid == 0) {
        float t = 0.f;
        #pragma unroll
        for (int w = 0; w < 8; w++) t += red2[w];
        s_inv = rsqrtf(t * (1.f / FFd) + 1e-5f);
    }
    __syncthreads();
    const float inv = s_inv;

    #pragma unroll
    for (int i = 0; i < 4; i++) {
        int c = tid + i*256;
        float x = (v[i] - mu) * inv * gw[c] + bw[c];
        hp[c] = 0.5f * x * (1.f + erff(x * 0.70710678118654752f));
    }
}

// ---------------- launcher ----------------
extern "C" void kernel_launch(void* const* d_in, const int* in_sizes, int n_in,
                              void* d_out, int out_size)
{
    const float* x0  = (const float*)d_in[0];
    const float* x1  = (const float*)d_in[1];
    const float* Wqk = (const float*)d_in[2];
    const float* bqk = (const float*)d_in[3];
    const float* Wv  = (const float*)d_in[4];
    const float* bv  = (const float*)d_in[5];
    const float* Wo  = (const float*)d_in[6];
    const float* bo  = (const float*)d_in[7];
    const float* Wf1 = (const float*)d_in[8];
    const float* bf1 = (const float*)d_in[9];
    const float* lng = (const float*)d_in[10];
    const float* lnb = (const float*)d_in[11];
    const float* Wf2 = (const float*)d_in[12];
    const float* bf2 = (const float*)d_in[13];
    float* out = (float*)d_out;

    float *qk0, *qk1, *v0, *v1, *a0, *a1, *hcat, *hmid;
    cudaGetSymbolAddress((void**)&qk0,  g_qk0);
    cudaGetSymbolAddress((void**)&qk1,  g_qk1);
    cudaGetSymbolAddress((void**)&v0,   g_v0);
    cudaGetSymbolAddress((void**)&v1,   g_v1);
    cudaGetSymbolAddress((void**)&a0,   g_a0);
    cudaGetSymbolAddress((void**)&a1,   g_a1);
    cudaGetSymbolAddress((void**)&hcat, g_hcat);
    cudaGetSymbolAddress((void**)&hmid, g_hmid);

    dim3 g512(Dmod/128, Mrows/128);   // (4, 64)
    dim3 g1024(FFd/128, Mrows/128);   // (8, 64)
    dim3 ga(Bsz*Hh, Nseq/64);         // (32, 32)
    int ctotal = Mrows * FFd;
    int cblocks = (ctotal + 255) / 256;

    // projections (shared qk projection applied to both streams)
    sgemm_bias_kernel<<<g512, 256>>>(x0, Wqk, bqk, nullptr, qk0, Mrows, Dmod, Dmod);
    sgemm_bias_kernel<<<g512, 256>>>(x1, Wqk, bqk, nullptr, qk1, Mrows, Dmod, Dmod);
    sgemm_bias_kernel<<<g512, 256>>>(x0, Wv,  bv,  nullptr, v0,  Mrows, Dmod, Dmod);
    sgemm_bias_kernel<<<g512, 256>>>(x1, Wv,  bv,  nullptr, v1,  Mrows, Dmod, Dmod);

    // cross attention
    attn_kernel<<<ga, 64>>>(qk0, qk1, v1, a0);
    attn_kernel<<<ga, 64>>>(qk1, qk0, v0, a1);

    // output projection (reuse v1/v0 as m0/m1 — their inputs are consumed)
    sgemm_bias_kernel<<<g512, 256>>>(a0, Wo, bo, nullptr, v1, Mrows, Dmod, Dmod);
    sgemm_bias_kernel<<<g512, 256>>>(a1, Wo, bo, nullptr, v0, Mrows, Dmod, Dmod);

    // FFN stream 0: y0 = x0 + FFN(concat(x0, m0))
    concat_kernel<<<cblocks, 256>>>(x0, v1, hcat);
    sgemm_bias_kernel<<<g1024, 256>>>(hcat, Wf1, bf1, nullptr, hmid, Mrows, FFd, FFd);
    ln_gelu_kernel<<<Mrows, 256>>>(hmid, lng, lnb);
    sgemm_bias_kernel<<<g512, 256>>>(hmid, Wf2, bf2, x0, out, Mrows, Dmod, FFd);

    // FFN stream 1: y1 = x1 + FFN(concat(x1, m1))
    concat_kernel<<<cblocks, 256>>>(x1, v0, hcat);
    sgemm_bias_kernel<<<g1024, 256>>>(hcat, Wf1, bf1, nullptr, hmid, Mrows, FFd, FFd);
    ln_gelu_kernel<<<Mrows, 256>>>(hmid, lng, lnb);
    sgemm_bias_kernel<<<g512, 256>>>(hmid, Wf2, bf2, x1, out + (size_t)Mrows*Dmod, Mrows, Dmod, FFd);
}

// round 2
// speedup vs baseline: 3.8771x; 3.8771x over previous
#include <cuda_runtime.h>
#include <math.h>
#include <stdint.h>

// Problem dims
#define Bsz  4
#define Nseq 2048
#define Dmod 512
#define Hh   8
#define DHd  64
#define FFd  1024
#define Mrows (Bsz*Nseq)   // 8192

// ---------------- scratch (static device allocations) ----------------
__device__ float g_qk0[Mrows*Dmod];
__device__ float g_qk1[Mrows*Dmod];
__device__ float g_v0 [Mrows*Dmod];
__device__ float g_v1 [Mrows*Dmod];
__device__ float g_a0 [Mrows*Dmod];
__device__ float g_a1 [Mrows*Dmod];
__device__ float g_hcat[Mrows*FFd];
__device__ float g_hmid[Mrows*FFd];

// ---------------- tf32 helpers ----------------
__device__ __forceinline__ float f2tf(float x) {
    uint32_t u;
    asm("cvt.rna.tf32.f32 %0, %1;" : "=r"(u) : "f"(x));
    return __uint_as_float(u);
}

__device__ __forceinline__ void mma_tf32(float d[4], const uint32_t a[4], const uint32_t b[2]) {
    asm volatile(
        "mma.sync.aligned.m16n8k8.row.col.f32.tf32.tf32.f32 "
        "{%0,%1,%2,%3}, {%4,%5,%6,%7}, {%8,%9}, {%0,%1,%2,%3};\n"
        : "+f"(d[0]), "+f"(d[1]), "+f"(d[2]), "+f"(d[3])
        : "r"(a[0]), "r"(a[1]), "r"(a[2]), "r"(a[3]), "r"(b[0]), "r"(b[1]));
}

// ---------------- TF32 GEMM: C[M,N] = A[M,K] * W[N,K]^T + bias (+res) ----------------
// 128x128 block tile, BK=32, 8 warps (2x4), each warp 64x32 (4x4 m16n8k8 atoms).
#define BM 128
#define BN 128
#define BK 32

__global__ __launch_bounds__(256) void gemm_tf32(
    const float* __restrict__ A, const float* __restrict__ W,
    const float* __restrict__ bias, const float* __restrict__ res,
    float* __restrict__ C, int M, int N, int K)
{
    __shared__ float As[BM][BK + 4];
    __shared__ float Bs[BN][BK + 4];

    const int tid  = threadIdx.x;
    const int wid  = tid >> 5, lane = tid & 31;
    const int g    = lane >> 2, tig = lane & 3;
    const int wm   = wid & 1,  wn  = wid >> 1;   // 2 x 4 warp grid

    const int lr = tid >> 3;         // 0..31 load row base
    const int lc = (tid & 7) * 4;    // 0..28 load col (float4)

    const float* Ag = A + (size_t)(blockIdx.y * BM + lr) * K + lc;
    const float* Wg = W + (size_t)(blockIdx.x * BN + lr) * K + lc;

    float acc[4][4][4];
    #pragma unroll
    for (int m = 0; m < 4; m++)
        #pragma unroll
        for (int n = 0; n < 4; n++)
            #pragma unroll
            for (int j = 0; j < 4; j++) acc[m][n][j] = 0.f;

    float4 ar[4], br[4];
    #pragma unroll
    for (int i = 0; i < 4; i++) {
        ar[i] = *(const float4*)(Ag + (size_t)i * 32 * K);
        br[i] = *(const float4*)(Wg + (size_t)i * 32 * K);
    }

    const int T = K / BK;
    for (int t = 0; t < T; t++) {
        __syncthreads();
        #pragma unroll
        for (int i = 0; i < 4; i++) {
            As[lr + 32*i][lc+0] = f2tf(ar[i].x); As[lr + 32*i][lc+1] = f2tf(ar[i].y);
            As[lr + 32*i][lc+2] = f2tf(ar[i].z); As[lr + 32*i][lc+3] = f2tf(ar[i].w);
            Bs[lr + 32*i][lc+0] = f2tf(br[i].x); Bs[lr + 32*i][lc+1] = f2tf(br[i].y);
            Bs[lr + 32*i][lc+2] = f2tf(br[i].z); Bs[lr + 32*i][lc+3] = f2tf(br[i].w);
        }
        __syncthreads();
        if (t + 1 < T) {
            #pragma unroll
            for (int i = 0; i < 4; i++) {
                ar[i] = *(const float4*)(Ag + (t+1)*BK + (size_t)i * 32 * K);
                br[i] = *(const float4*)(Wg + (t+1)*BK + (size_t)i * 32 * K);
            }
        }
        #pragma unroll
        for (int kq = 0; kq < 4; kq++) {
            uint32_t af[4][4], bf[4][2];
            #pragma unroll
            for (int m = 0; m < 4; m++) {
                int r = wm*64 + m*16 + g;
                af[m][0] = __float_as_uint(As[r    ][kq*8 + tig]);
                af[m][1] = __float_as_uint(As[r + 8][kq*8 + tig]);
                af[m][2] = __float_as_uint(As[r    ][kq*8 + tig + 4]);
                af[m][3] = __float_as_uint(As[r + 8][kq*8 + tig + 4]);
            }
            #pragma unroll
            for (int n = 0; n < 4; n++) {
                int r = wn*32 + n*8 + g;
                bf[n][0] = __float_as_uint(Bs[r][kq*8 + tig]);
                bf[n][1] = __float_as_uint(Bs[r][kq*8 + tig + 4]);
            }
            #pragma unroll
            for (int m = 0; m < 4; m++)
                #pragma unroll
                for (int n = 0; n < 4; n++)
                    mma_tf32(acc[m][n], af[m], bf[n]);
        }
    }

    const int rb = blockIdx.y * BM + wm * 64;
    const int cb = blockIdx.x * BN + wn * 32;
    #pragma unroll
    for (int m = 0; m < 4; m++) {
        #pragma unroll
        for (int n = 0; n < 4; n++) {
            int row0 = rb + m*16 + g;
            int col  = cb + n*8 + tig*2;
            float b0 = bias[col], b1 = bias[col+1];
            float v0 = acc[m][n][0] + b0, v1 = acc[m][n][1] + b1;
            float v2 = acc[m][n][2] + b0, v3 = acc[m][n][3] + b1;
            if (res) {
                const float* r0p = res + (size_t)row0 * N + col;
                const float* r1p = res + (size_t)(row0+8) * N + col;
                v0 += r0p[0]; v1 += r0p[1];
                v2 += r1p[0]; v3 += r1p[1];
            }
            *(float2*)(C + (size_t)row0     * N + col) = make_float2(v0, v1);
            *(float2*)(C + (size_t)(row0+8) * N + col) = make_float2(v2, v3);
        }
    }
}

// ---------------- Tensor-core flash attention (tf32) ----------------
// Block: 256 threads, 8 warps; 128 q-rows per block (warp owns 16 rows x full width).
// Key tiles of 64. S via mma -> warp-local online softmax -> P through smem -> PV mma.
#define KT 64
#define ATTN_SMEM ((2*KT*68 + 128*68) * 4)   // Ks + Vs + Ps = 69632 bytes

__global__ __launch_bounds__(256) void attn_tc(
    const float* __restrict__ Q, const float* __restrict__ Kt,
    const float* __restrict__ V, float* __restrict__ O)
{
    extern __shared__ float smbuf[];
    float (*Ks)[68] = (float(*)[68])smbuf;                 // KT x 68
    float (*Vs)[68] = (float(*)[68])(smbuf + KT*68);       // KT x 68
    float (*Ps)[68] = (float(*)[68])(smbuf + 2*KT*68);     // 128 x 68

    const int tid  = threadIdx.x;
    const int wid  = tid >> 5, lane = tid & 31;
    const int g    = lane >> 2, tig = lane & 3;

    const int bh = blockIdx.x;
    const int b  = bh >> 3, h = bh & 7;
    const size_t base = (size_t)b * (Nseq * Dmod) + (size_t)h * DHd;
    const int qrow = blockIdx.y * 128 + wid * 16;

    // Q fragments (warp's 16 rows x 64 cols), kept in registers for all key tiles
    uint32_t qf[8][4];
    {
        const float* qp = Q + base + (size_t)(qrow + g) * Dmod;
        #pragma unroll
        for (int ks = 0; ks < 8; ks++) {
            qf[ks][0] = __float_as_uint(f2tf(qp[ks*8 + tig]));
            qf[ks][1] = __float_as_uint(f2tf(qp[8*Dmod + ks*8 + tig]));
            qf[ks][2] = __float_as_uint(f2tf(qp[ks*8 + tig + 4]));
            qf[ks][3] = __float_as_uint(f2tf(qp[8*Dmod + ks*8 + tig + 4]));
        }
    }

    float oacc[8][4];
    #pragma unroll
    for (int n = 0; n < 8; n++)
        #pragma unroll
        for (int j = 0; j < 4; j++) oacc[n][j] = 0.f;
    float m0 = -1e30f, m1 = -1e30f, l0 = 0.f, l1 = 0.f;

    const int lr = tid >> 2;          // 0..63
    const int lc = (tid & 3) * 4;     // 0,4,8,12 (+16*i)
    const float* Kg = Kt + base + (size_t)lr * Dmod + lc;
    const float* Vg = V  + base + (size_t)lr * Dmod + lc;

    const int pr = wid * 16 + g;

    for (int kt = 0; kt < Nseq / KT; kt++) {
        __syncthreads();
        size_t off = (size_t)kt * KT * Dmod;
        #pragma unroll
        for (int i = 0; i < 4; i++) {
            float4 kv = *(const float4*)(Kg + off + i*16);
            float4 vv = *(const float4*)(Vg + off + i*16);
            Ks[lr][lc + 16*i + 0] = f2tf(kv.x); Ks[lr][lc + 16*i + 1] = f2tf(kv.y);
            Ks[lr][lc + 16*i + 2] = f2tf(kv.z); Ks[lr][lc + 16*i + 3] = f2tf(kv.w);
            Vs[lr][lc + 16*i + 0] = f2tf(vv.x); Vs[lr][lc + 16*i + 1] = f2tf(vv.y);
            Vs[lr][lc + 16*i + 2] = f2tf(vv.z); Vs[lr][lc + 16*i + 3] = f2tf(vv.w);
        }
        __syncthreads();

        // S = Q K^T  (warp: 16 rows x 64 keys)
        float sacc[8][4];
        #pragma unroll
        for (int n = 0; n < 8; n++)
            #pragma unroll
            for (int j = 0; j < 4; j++) sacc[n][j] = 0.f;

        #pragma unroll
        for (int ks = 0; ks < 8; ks++) {
            uint32_t bf[8][2];
            #pragma unroll
            for (int n = 0; n < 8; n++) {
                bf[n][0] = __float_as_uint(Ks[n*8 + g][ks*8 + tig]);
                bf[n][1] = __float_as_uint(Ks[n*8 + g][ks*8 + tig + 4]);
            }
            #pragma unroll
            for (int n = 0; n < 8; n++) mma_tf32(sacc[n], qf[ks], bf[n]);
        }

        // online softmax (rows g and g+8 of warp tile)
        float t0 = -1e30f, t1 = -1e30f;
        #pragma unroll
        for (int n = 0; n < 8; n++) {
            sacc[n][0] *= 0.125f; sacc[n][1] *= 0.125f;
            sacc[n][2] *= 0.125f; sacc[n][3] *= 0.125f;
            t0 = fmaxf(t0, fmaxf(sacc[n][0], sacc[n][1]));
            t1 = fmaxf(t1, fmaxf(sacc[n][2], sacc[n][3]));
        }
        t0 = fmaxf(t0, __shfl_xor_sync(0xffffffffu, t0, 1));
        t0 = fmaxf(t0, __shfl_xor_sync(0xffffffffu, t0, 2));
        t1 = fmaxf(t1, __shfl_xor_sync(0xffffffffu, t1, 1));
        t1 = fmaxf(t1, __shfl_xor_sync(0xffffffffu, t1, 2));

        float mn0 = fmaxf(m0, t0), mn1 = fmaxf(m1, t1);
        float c0 = __expf(m0 - mn0), c1 = __expf(m1 - mn1);
        m0 = mn0; m1 = mn1;

        float ps0 = 0.f, ps1 = 0.f;
        #pragma unroll
        for (int n = 0; n < 8; n++) {
            float p00 = __expf(sacc[n][0] - m0), p01 = __expf(sacc[n][1] - m0);
            float p10 = __expf(sacc[n][2] - m1), p11 = __expf(sacc[n][3] - m1);
            ps0 += p00 + p01; ps1 += p10 + p11;
            sacc[n][0] = p00; sacc[n][1] = p01; sacc[n][2] = p10; sacc[n][3] = p11;
        }
        ps0 += __shfl_xor_sync(0xffffffffu, ps0, 1);
        ps0 += __shfl_xor_sync(0xffffffffu, ps0, 2);
        ps1 += __shfl_xor_sync(0xffffffffu, ps1, 1);
        ps1 += __shfl_xor_sync(0xffffffffu, ps1, 2);
        l0 = l0 * c0 + ps0;
        l1 = l1 * c1 + ps1;
        #pragma unroll
        for (int n = 0; n < 8; n++) {
            oacc[n][0] *= c0; oacc[n][1] *= c0;
            oacc[n][2] *= c1; oacc[n][3] *= c1;
        }

        // write P tile to smem (A-operand for PV)
        #pragma unroll
        for (int n = 0; n < 8; n++) {
            Ps[pr    ][n*8 + tig*2    ] = f2tf(sacc[n][0]);
            Ps[pr    ][n*8 + tig*2 + 1] = f2tf(sacc[n][1]);
            Ps[pr + 8][n*8 + tig*2    ] = f2tf(sacc[n][2]);
            Ps[pr + 8][n*8 + tig*2 + 1] = f2tf(sacc[n][3]);
        }
        __syncthreads();

        // O += P V
        #pragma unroll
        for (int ks = 0; ks < 8; ks++) {
            uint32_t af[4];
            af[0] = __float_as_uint(Ps[pr    ][ks*8 + tig]);
            af[1] = __float_as_uint(Ps[pr + 8][ks*8 + tig]);
            af[2] = __float_as_uint(Ps[pr    ][ks*8 + tig + 4]);
            af[3] = __float_as_uint(Ps[pr + 8][ks*8 + tig + 4]);
            #pragma unroll
            for (int n = 0; n < 8; n++) {
                uint32_t bf[2];
                bf[0] = __float_as_uint(Vs[ks*8 + tig    ][n*8 + g]);
                bf[1] = __float_as_uint(Vs[ks*8 + tig + 4][n*8 + g]);
                mma_tf32(oacc[n], af, bf);
            }
        }
    }

    float i0 = 1.f / l0, i1 = 1.f / l1;
    float* Op = O + base + (size_t)(qrow + g) * Dmod;
    #pragma unroll
    for (int n = 0; n < 8; n++) {
        *(float2*)(Op + n*8 + tig*2)            = make_float2(oacc[n][0]*i0, oacc[n][1]*i0);
        *(float2*)(Op + 8*Dmod + n*8 + tig*2)   = make_float2(oacc[n][2]*i1, oacc[n][3]*i1);
    }
}

// ---------------- concat [x | m] -> hcat [M, 1024] ----------------
__global__ void concat_kernel(const float* __restrict__ X, const float* __restrict__ Mm,
                              float* __restrict__ Out)
{
    int idx = blockIdx.x * blockDim.x + threadIdx.x;
    if (idx >= Mrows * FFd) return;
    int m = idx >> 10;
    int c = idx & 1023;
    Out[idx] = (c < Dmod) ? X[(size_t)m * Dmod + c] : Mm[(size_t)m * Dmod + (c - Dmod)];
}

// ---------------- LayerNorm(1024) + exact GELU, in place ----------------
__global__ __launch_bounds__(256) void ln_gelu_kernel(
    float* __restrict__ Hm, const float* __restrict__ gw, const float* __restrict__ bw)
{
    __shared__ float red1[8];
    __shared__ float red2[8];
    __shared__ float s_mu, s_inv;

    const int row = blockIdx.x;
    const int tid = threadIdx.x;
    float* hp = Hm + (size_t)row * FFd;

    float v[4];
    float s = 0.f;
    #pragma unroll
    for (int i = 0; i < 4; i++) { v[i] = hp[tid + i*256]; s += v[i]; }

    #pragma unroll
    for (int off = 16; off; off >>= 1) s += __shfl_xor_sync(0xffffffffu, s, off);
    if ((tid & 31) == 0) red1[tid >> 5] = s;
    __syncthreads();
    if (tid == 0) {
        float t = 0.f;
        #pragma unroll
        for (int w = 0; w < 8; w++) t += red1[w];
        s_mu = t * (1.f / FFd);
    }
    __syncthreads();
    const float mu = s_mu;

    float ss = 0.f;
    #pragma unroll
    for (int i = 0; i < 4; i++) { float d = v[i] - mu; ss += d*d; }
    #pragma unroll
    for (int off = 16; off; off >>= 1) ss += __shfl_xor_sync(0xffffffffu, ss, off);
    if ((tid & 31) == 0) red2[tid >> 5] = ss;
    __syncthreads();
    if (tid == 0) {
        float t = 0.f;
        #pragma unroll
        for (int w = 0; w < 8; w++) t += red2[w];
        s_inv = rsqrtf(t * (1.f / FFd) + 1e-5f);
    }
    __syncthreads();
    const float inv = s_inv;

    #pragma unroll
    for (int i = 0; i < 4; i++) {
        int c = tid + i*256;
        float x = (v[i] - mu) * inv * gw[c] + bw[c];
        hp[c] = 0.5f * x * (1.f + erff(x * 0.70710678118654752f));
    }
}

// ---------------- launcher ----------------
extern "C" void kernel_launch(void* const* d_in, const int* in_sizes, int n_in,
                              void* d_out, int out_size)
{
    const float* x0  = (const float*)d_in[0];
    const float* x1  = (const float*)d_in[1];
    const float* Wqk = (const float*)d_in[2];
    const float* bqk = (const float*)d_in[3];
    const float* Wv  = (const float*)d_in[4];
    const float* bv  = (const float*)d_in[5];
    const float* Wo  = (const float*)d_in[6];
    const float* bo  = (const float*)d_in[7];
    const float* Wf1 = (const float*)d_in[8];
    const float* bf1 = (const float*)d_in[9];
    const float* lng = (const float*)d_in[10];
    const float* lnb = (const float*)d_in[11];
    const float* Wf2 = (const float*)d_in[12];
    const float* bf2 = (const float*)d_in[13];
    float* out = (float*)d_out;

    float *qk0, *qk1, *v0, *v1, *a0, *a1, *hcat, *hmid;
    cudaGetSymbolAddress((void**)&qk0,  g_qk0);
    cudaGetSymbolAddress((void**)&qk1,  g_qk1);
    cudaGetSymbolAddress((void**)&v0,   g_v0);
    cudaGetSymbolAddress((void**)&v1,   g_v1);
    cudaGetSymbolAddress((void**)&a0,   g_a0);
    cudaGetSymbolAddress((void**)&a1,   g_a1);
    cudaGetSymbolAddress((void**)&hcat, g_hcat);
    cudaGetSymbolAddress((void**)&hmid, g_hmid);

    cudaFuncSetAttribute(attn_tc, cudaFuncAttributeMaxDynamicSharedMemorySize, ATTN_SMEM);

    dim3 g512(Dmod/128, Mrows/128);   // (4, 64)
    dim3 g1024(FFd/128, Mrows/128);   // (8, 64)
    dim3 ga(Bsz*Hh, Nseq/128);        // (32, 16)
    int ctotal = Mrows * FFd;
    int cblocks = (ctotal + 255) / 256;

    // projections
    gemm_tf32<<<g512, 256>>>(x0, Wqk, bqk, nullptr, qk0, Mrows, Dmod, Dmod);
    gemm_tf32<<<g512, 256>>>(x1, Wqk, bqk, nullptr, qk1, Mrows, Dmod, Dmod);
    gemm_tf32<<<g512, 256>>>(x0, Wv,  bv,  nullptr, v0,  Mrows, Dmod, Dmod);
    gemm_tf32<<<g512, 256>>>(x1, Wv,  bv,  nullptr, v1,  Mrows, Dmod, Dmod);

    // cross attention
    attn_tc<<<ga, 256, ATTN_SMEM>>>(qk0, qk1, v1, a0);
    attn_tc<<<ga, 256, ATTN_SMEM>>>(qk1, qk0, v0, a1);

    // output projection (reuse v1/v0 as m0/m1)
    gemm_tf32<<<g512, 256>>>(a0, Wo, bo, nullptr, v1, Mrows, Dmod, Dmod);
    gemm_tf32<<<g512, 256>>>(a1, Wo, bo, nullptr, v0, Mrows, Dmod, Dmod);

    // FFN stream 0
    concat_kernel<<<cblocks, 256>>>(x0, v1, hcat);
    gemm_tf32<<<g1024, 256>>>(hcat, Wf1, bf1, nullptr, hmid, Mrows, FFd, FFd);
    ln_gelu_kernel<<<Mrows, 256>>>(hmid, lng, lnb);
    gemm_tf32<<<g512, 256>>>(hmid, Wf2, bf2, x0, out, Mrows, Dmod, FFd);

    // FFN stream 1
    concat_kernel<<<cblocks, 256>>>(x1, v0, hcat);
    gemm_tf32<<<g1024, 256>>>(hcat, Wf1, bf1, nullptr, hmid, Mrows, FFd, FFd);
    ln_gelu_kernel<<<Mrows, 256>>>(hmid, lng, lnb);
    gemm_tf32<<<g512, 256>>>(hmid, Wf2, bf2, x1, out + (size_t)Mrows*Dmod, Mrows, Dmod, FFd);
}